// round 13
// baseline (speedup 1.0000x reference)
#include <cuda_runtime.h>
#include <stdint.h>

#define GRID_N 256

// dx = fp32(20/255); R = fp32(1/dx). XLA rewrites A/dx -> A*(1/dx), constant-folded.
#define DXF (20.0f / 255.0f)
#define RF  (1.0f / DXF)

__device__ __forceinline__ uint64_t make_evict_last_policy()
{
    uint64_t p;
    asm("createpolicy.fractional.L2::evict_last.b64 %0, 1.0;" : "=l"(p));
    return p;
}

// NOTE: no "memory" clobber — grid is never read in the scatter kernel, so the
// compiler may hoist position/weight loads across REDG bursts (interleaving
// load issue with the ~41-cyc LSU drain of each spread REDG).
__device__ __forceinline__ void red_add_evict_last(float* addr, float v, uint64_t policy)
{
    asm volatile("red.global.add.L2::cache_hint.f32 [%0], %1, %2;"
                 :: "l"(addr), "f"(v), "l"(policy));
}

__device__ __forceinline__ void st_zero4_evict_last(float4* addr, uint64_t policy)
{
    asm volatile("st.global.L2::cache_hint.v4.f32 [%0], {%1, %1, %1, %1}, %2;"
                 :: "l"(addr), "f"(0.0f), "l"(policy) : "memory");
}

// Zero the grid with evict_last priority: parks all 67MB in L2 at top retention
// priority before the particle stream competes for capacity.
__global__ void __launch_bounds__(256) zero_grid_kernel(float* __restrict__ grid, int n_cells)
{
    uint64_t policy = make_evict_last_policy();
    int t = blockIdx.x * blockDim.x + threadIdx.x;
    int stride = gridDim.x * blockDim.x;
    int n4 = n_cells / 4;
    float4* g4 = (float4*)grid;
    for (int i = t; i < n4; i += stride)
        st_zero4_evict_last(&g4[i], policy);
}

// flat cell index, or -1 if out of grid
__device__ __forceinline__ int cell_index(float px, float py, float pz)
{
    // fi = (p + 10) * R ; then fi + 0.5, trunc toward zero.
    // __fmul_rn/__fadd_rn forbid FFMA contraction (XLA emits separate mul/add).
    float fx = __fadd_rn(__fmul_rn(__fadd_rn(px, 10.0f), RF), 0.5f);
    float fy = __fadd_rn(__fmul_rn(__fadd_rn(py, 10.0f), RF), 0.5f);
    float fz = __fadd_rn(__fmul_rn(__fadd_rn(pz, 10.0f), RF), 0.5f);

    int ix = (int)fx;   // cvt.rzi: trunc toward zero == astype(int32)
    int iy = (int)fy;
    int iz = (int)fz;

    bool in_grid = (ix >= 0) & (ix < GRID_N) &
                   (iy >= 0) & (iy < GRID_N) &
                   (iz >= 0) & (iz < GRID_N);
    return in_grid ? (ix * GRID_N + iy) * GRID_N + iz : -1;
}

__device__ __forceinline__ void load_batch(
    const float4* __restrict__ p4, const float4* __restrict__ w4, int g,
    int idx[4], float wt[4])
{
    float4 a = __ldcs(&p4[3 * g + 0]);
    float4 b = __ldcs(&p4[3 * g + 1]);
    float4 c = __ldcs(&p4[3 * g + 2]);
    float4 w = __ldcs(&w4[g]);

    idx[0] = cell_index(a.x, a.y, a.z); wt[0] = w.x;
    idx[1] = cell_index(a.w, b.x, b.y); wt[1] = w.y;
    idx[2] = cell_index(b.z, b.w, c.x); wt[2] = w.z;
    idx[3] = cell_index(c.y, c.z, c.w); wt[3] = w.w;
}

// Persistent grid-stride, software-pipelined: load batch g+1, deposit batch g.
// The ~164 cyc of REDG LSU drain per batch hides the next batch's load latency.
__global__ void __launch_bounds__(256, 8) scatter_kernel_pipe(
    const float* __restrict__ positions,  // [N,3]
    const float* __restrict__ weights,    // [N]
    float* __restrict__ grid,
    int n_groups,
    int n_particles)
{
    const float4* p4 = (const float4*)positions;
    const float4* w4 = (const float4*)weights;
    uint64_t policy = make_evict_last_policy();

    int stride = gridDim.x * blockDim.x;
    int t = blockIdx.x * blockDim.x + threadIdx.x;

    int cur_idx[4];
    float cur_wt[4];

    int g = t;
    if (g < n_groups) {
        load_batch(p4, w4, g, cur_idx, cur_wt);
        for (g += stride; g < n_groups; g += stride) {
            int nidx[4];
            float nwt[4];
            load_batch(p4, w4, g, nidx, nwt);   // loads issue before REDG burst
            #pragma unroll
            for (int j = 0; j < 4; j++)
                if (cur_idx[j] >= 0) red_add_evict_last(&grid[cur_idx[j]], cur_wt[j], policy);
            #pragma unroll
            for (int j = 0; j < 4; j++) { cur_idx[j] = nidx[j]; cur_wt[j] = nwt[j]; }
        }
        #pragma unroll
        for (int j = 0; j < 4; j++)
            if (cur_idx[j] >= 0) red_add_evict_last(&grid[cur_idx[j]], cur_wt[j], policy);
    }

    // Tail particles (n_particles % 4)
    int tail_start = n_groups * 4;
    for (int i = tail_start + t; i < n_particles; i += stride) {
        float px = __ldcs(&positions[3 * i + 0]);
        float py = __ldcs(&positions[3 * i + 1]);
        float pz = __ldcs(&positions[3 * i + 2]);
        float w  = __ldcs(&weights[i]);
        int idx = cell_index(px, py, pz);
        if (idx >= 0) red_add_evict_last(&grid[idx], w, policy);
    }
}

extern "C" void kernel_launch(void* const* d_in, const int* in_sizes, int n_in,
                              void* d_out, int out_size)
{
    const float* positions = (const float*)d_in[0];
    const float* weights   = (const float*)d_in[1];
    float* grid            = (float*)d_out;

    int n_particles = in_sizes[1];  // weights has N elements; positions has 3N
    int n_groups = n_particles / 4;

    {
        int threads = 256;
        int blocks = 148 * 8;
        zero_grid_kernel<<<blocks, threads>>>(grid, out_size);
    }

    // One full wave: 148 SMs x 8 CTAs x 256 threads (launch_bounds caps regs for occ=100%)
    int threads = 256;
    int blocks = 148 * 8;
    scatter_kernel_pipe<<<blocks, threads>>>(positions, weights, grid, n_groups, n_particles);
}

// round 14
// speedup vs baseline: 1.0742x; 1.0742x over previous
#include <cuda_runtime.h>
#include <stdint.h>

#define GRID_N 256

// dx = fp32(20/255); R = fp32(1/dx). XLA rewrites A/dx -> A*(1/dx), constant-folded.
#define DXF (20.0f / 255.0f)
#define RF  (1.0f / DXF)

__device__ __forceinline__ uint64_t make_evict_last_policy()
{
    uint64_t p;
    asm("createpolicy.fractional.L2::evict_last.b64 %0, 1.0;" : "=l"(p));
    return p;
}

__device__ __forceinline__ void red_add_evict_last(float* addr, float v, uint64_t policy)
{
    asm volatile("red.global.add.L2::cache_hint.f32 [%0], %1, %2;"
                 :: "l"(addr), "f"(v), "l"(policy) : "memory");
}

__device__ __forceinline__ void st_zero4_evict_last(float4* addr, uint64_t policy)
{
    asm volatile("st.global.L2::cache_hint.v4.f32 [%0], {%1, %1, %1, %1}, %2;"
                 :: "l"(addr), "f"(0.0f), "l"(policy) : "memory");
}

// Zero the grid with evict_last priority. Maximally wide: ONE float4 store per
// thread, no loop — 16384 CTAs dispatch across all SMs so the LTS-capped store
// stream finishes with minimal tail.
__global__ void __launch_bounds__(256) zero_grid_kernel_wide(float* __restrict__ grid, int n4)
{
    int t = blockIdx.x * blockDim.x + threadIdx.x;
    if (t < n4) {
        uint64_t policy = make_evict_last_policy();
        st_zero4_evict_last(&((float4*)grid)[t], policy);
    }
}

__device__ __forceinline__ void deposit(float px, float py, float pz, float w,
                                        float* __restrict__ grid, uint64_t policy)
{
    // fi = (p + 10) * R ; then fi + 0.5, trunc toward zero.
    // __fmul_rn/__fadd_rn forbid FFMA contraction (XLA emits separate mul/add).
    float fx = __fadd_rn(__fmul_rn(__fadd_rn(px, 10.0f), RF), 0.5f);
    float fy = __fadd_rn(__fmul_rn(__fadd_rn(py, 10.0f), RF), 0.5f);
    float fz = __fadd_rn(__fmul_rn(__fadd_rn(pz, 10.0f), RF), 0.5f);

    int ix = (int)fx;   // cvt.rzi: trunc toward zero == astype(int32)
    int iy = (int)fy;
    int iz = (int)fz;

    bool in_grid = (ix >= 0) & (ix < GRID_N) &
                   (iy >= 0) & (iy < GRID_N) &
                   (iz >= 0) & (iz < GRID_N);
    if (in_grid) {
        int flat = (ix * GRID_N + iy) * GRID_N + iz;
        red_add_evict_last(&grid[flat], w, policy);
    }
}

// Best-measured scatter config (R11): 4 particles/thread, float4 loads with
// evict_first streaming, evict_last REDG, non-persistent launch.
__global__ void __launch_bounds__(256, 8) scatter_kernel_v4p(
    const float* __restrict__ positions,  // [N,3]
    const float* __restrict__ weights,    // [N]
    float* __restrict__ grid,
    int n_particles)
{
    int t = blockIdx.x * blockDim.x + threadIdx.x;
    int base = 4 * t;
    uint64_t policy = make_evict_last_policy();

    if (base + 3 < n_particles) {
        const float4* p4 = (const float4*)positions;
        float4 a = __ldcs(&p4[3 * t + 0]);
        float4 b = __ldcs(&p4[3 * t + 1]);
        float4 c = __ldcs(&p4[3 * t + 2]);
        float4 w = __ldcs(&((const float4*)weights)[t]);

        deposit(a.x, a.y, a.z, w.x, grid, policy);
        deposit(a.w, b.x, b.y, w.y, grid, policy);
        deposit(b.z, b.w, c.x, w.z, grid, policy);
        deposit(c.y, c.z, c.w, w.w, grid, policy);
    } else if (base < n_particles) {
        for (int i = base; i < n_particles; i++) {
            float px = __ldcs(&positions[3 * i + 0]);
            float py = __ldcs(&positions[3 * i + 1]);
            float pz = __ldcs(&positions[3 * i + 2]);
            float w  = __ldcs(&weights[i]);
            deposit(px, py, pz, w, grid, policy);
        }
    }
}

extern "C" void kernel_launch(void* const* d_in, const int* in_sizes, int n_in,
                              void* d_out, int out_size)
{
    const float* positions = (const float*)d_in[0];
    const float* weights   = (const float*)d_in[1];
    float* grid            = (float*)d_out;

    int n_particles = in_sizes[1];  // weights has N elements; positions has 3N

    // Zero + park grid in L2 with evict_last priority (maximally wide launch).
    {
        int n4 = out_size / 4;   // 16,777,216 / 4 = 4,194,304 float4 stores
        int threads = 256;
        int blocks = (n4 + threads - 1) / threads;
        zero_grid_kernel_wide<<<blocks, threads>>>(grid, n4);
    }

    int threads = 256;
    int n_threads_total = (n_particles + 3) / 4;
    int blocks = (n_threads_total + threads - 1) / threads;
    scatter_kernel_v4p<<<blocks, threads>>>(positions, weights, grid, n_particles);
}